// round 8
// baseline (speedup 1.0000x reference)
#include <cuda_runtime.h>
#include <math.h>
#include <stdint.h>

// ---------------------------------------------------------------------------
// MultiHeadCrossAttentionBlock: B=4, S=2048, D=512, H=8, DK=64
// d_out = out [B,S,D] ++ attn.mean(axis=1) [B,S,S]
//
// Round 7: tcgen05 is unavailable (harness PTX target is sm_103, not
// sm_103a -> all tcgen05.* rejected) and legacy mma.sync measured too slow
// (R4). New lever: packed dual-fp32 FMA (SASS FFMA2) via PTX fma.rn.f32x2,
// which ptxas never emits from C++. k1/k5 inner loops converted (their 8x8
// micro-tiles have the 1B/MAC intensity FFMA2 needs). k2/k3 unchanged from
// the 1851us round-5 build.
// ---------------------------------------------------------------------------

namespace cfg {
constexpr int B  = 4;
constexpr int S  = 2048;
constexpr int D  = 512;
constexpr int H  = 8;
constexpr int DK = 64;
constexpr int N3 = 3 * D;          // 1536
constexpr int MROWS = B * S;       // 8192
constexpr float SCALE = 0.125f;
constexpr int TQ = 16;
constexpr int TK = 256;
constexpr int NCH = S / TK;
constexpr int SROW = S + 4;
constexpr int SMEM2_FLOATS = TQ * SROW + DK * TK + DK * 20;
constexpr int SMEM2 = SMEM2_FLOATS * 4;
constexpr int HGRP = H / 2;
}

// ------------------------------ scratch ------------------------------------
__device__ float g_Q [cfg::B * cfg::H * cfg::S * cfg::DK];
__device__ float g_Kt[cfg::B * cfg::H * cfg::DK * cfg::S];
__device__ float g_V [cfg::B * cfg::H * cfg::S * cfg::DK];
__device__ float g_ctx[cfg::B * cfg::S * cfg::D];
__device__ float g_attn2[(size_t)cfg::B * cfg::S * cfg::S];

// ---------------------------------------------------------------------------
// packed f32x2 helpers (SASS FFMA2 — only reachable via PTX fma.rn.f32x2)
// ---------------------------------------------------------------------------
__device__ __forceinline__ void ffma2(unsigned long long& d,
                                      unsigned long long a,
                                      unsigned long long b) {
    asm("fma.rn.f32x2 %0, %1, %2, %0;" : "+l"(d) : "l"(a), "l"(b));
}
__device__ __forceinline__ unsigned long long pack2(float x) {
    unsigned long long r;
    asm("mov.b64 %0, {%1, %1};" : "=l"(r) : "f"(x));
    return r;
}
__device__ __forceinline__ float2 unpack2(unsigned long long v) {
    float lo, hi;
    asm("mov.b64 {%0, %1}, %2;" : "=f"(lo), "=f"(hi) : "l"(v));
    return make_float2(lo, hi);
}

// ---------------------------------------------------------------------------
// K1: QKV projection. C[8192,1536] = Z @ Wqkv  (Z = Zq for n<512, else Zkv)
// 128x128x16 tiles, 256 threads, 8x8 micro-tile, FFMA2 inner loop.
// ---------------------------------------------------------------------------
__global__ __launch_bounds__(256) void k1_qkv(
    const float* __restrict__ Zq, const float* __restrict__ Zkv,
    const float* __restrict__ W)
{
    using namespace cfg;
    constexpr int BM = 128, BN = 128, BK = 16;
    __shared__ float As[BK][BM + 4];
    __shared__ float Bs[BK][BN];

    const int row0 = blockIdx.x * BM;
    const int col0 = blockIdx.y * BN;
    const float* __restrict__ Z = (col0 < D) ? Zq : Zkv;

    const int t  = threadIdx.x;
    const int tm = (t >> 4) << 3;
    const int tn = (t & 15) << 3;

    unsigned long long acc2[8][4];
#pragma unroll
    for (int i = 0; i < 8; i++)
#pragma unroll
        for (int j = 0; j < 4; j++) acc2[i][j] = 0ULL;

    for (int k0 = 0; k0 < D; k0 += BK) {
#pragma unroll
        for (int i = 0; i < 8; i++) {           // A tile: 128x16
            int p = t + i * 256;
            int m = p >> 4, k = p & 15;
            As[k][m] = Z[(size_t)(row0 + m) * D + k0 + k];
        }
#pragma unroll
        for (int i = 0; i < 8; i++) {           // B tile: 16x128
            int p = t + i * 256;
            int k = p >> 7, n = p & 127;
            Bs[k][n] = W[(size_t)(k0 + k) * N3 + col0 + n];
        }
        __syncthreads();
#pragma unroll
        for (int k = 0; k < BK; k++) {
            const ulonglong2 bl = *(const ulonglong2*)&Bs[k][tn];
            const ulonglong2 bh = *(const ulonglong2*)&Bs[k][tn + 4];
            const unsigned long long bb0 = bl.x, bb1 = bl.y;
            const unsigned long long bb2 = bh.x, bb3 = bh.y;
            float a[8];
#pragma unroll
            for (int i = 0; i < 8; i++) a[i] = As[k][tm + i];
#pragma unroll
            for (int i = 0; i < 8; i++) {
                const unsigned long long aa = pack2(a[i]);
                ffma2(acc2[i][0], aa, bb0);
                ffma2(acc2[i][1], aa, bb1);
                ffma2(acc2[i][2], aa, bb2);
                ffma2(acc2[i][3], aa, bb3);
            }
        }
        __syncthreads();
    }

    const int part = col0 / D;                  // 0=Q, 1=K, 2=V (block-uniform)
#pragma unroll
    for (int i = 0; i < 8; i++) {
        const int r = row0 + tm + i;
        const int b = r >> 11, s = r & (S - 1);
#pragma unroll
        for (int jp = 0; jp < 4; jp++) {
            const float2 v2 = unpack2(acc2[i][jp]);
            const float vv[2] = {v2.x, v2.y};
#pragma unroll
            for (int e = 0; e < 2; e++) {
                const int c  = col0 + tn + 2 * jp + e - part * D;
                const int h  = c >> 6, dk = c & 63;
                const float v = vv[e];
                if (part == 0)      g_Q [((size_t)(b * H + h) * S  + s)  * DK + dk] = v;
                else if (part == 1) g_Kt[((size_t)(b * H + h) * DK + dk) * S  + s ] = v;
                else                g_V [((size_t)(b * H + h) * S  + s)  * DK + dk] = v;
            }
        }
    }
}

// ---------------------------------------------------------------------------
// K2: fused attention (unchanged from round 5; 1851us build)
// ---------------------------------------------------------------------------
__global__ __launch_bounds__(256, 1) void k2_attn(
    const float* __restrict__ mask, float* __restrict__ attn_out)
{
    using namespace cfg;
    extern __shared__ float sm[];
    float* Ss  = sm;
    float* KVs = Ss + TQ * SROW;
    float* Qs  = KVs + DK * TK;

    const int qt = blockIdx.x;
    const int b  = blockIdx.y;
    const int hz = blockIdx.z;
    const int h0 = hz * HGRP;
    const int q0 = qt * TQ;
    const int t  = threadIdx.x;

    float* __restrict__ attn_dst = (hz == 0) ? attn_out : g_attn2;

    const int qi = t >> 6;
    const int ki = t & 63;
    const int kq  = t >> 6;
    const int qg4 = ((t >> 4) & 3) << 2;
    const int cg4 = (t & 15) << 2;
    const int w = t >> 5, lane = t & 31;

    float4 pf[16];

    for (int hh = 0; hh < HGRP; hh++) {
        const int h  = h0 + hh;
        const int bh = b * H + h;
        const float* __restrict__ Qg  = g_Q  + ((size_t)bh * S + q0) * DK;
        const float* __restrict__ Ktg = g_Kt + (size_t)bh * DK * S;
        const float* __restrict__ Vg  = g_V  + (size_t)bh * S * DK;

#pragma unroll
        for (int i = 0; i < 4; i++) {
            int p = t + i * 256;
            int q = p >> 6, d = p & 63;
            Qs[d * 20 + q] = Qg[q * DK + d];
        }

#pragma unroll
        for (int i = 0; i < 16; i++) {
            int p4 = t + (i << 8);
            pf[i] = *(const float4*)&Ktg[(size_t)(p4 >> 6) * S + ((p4 & 63) << 2)];
        }

        for (int c = 0; c < NCH; c++) {
            const int kc = c * TK;
            __syncthreads();
#pragma unroll
            for (int i = 0; i < 16; i++) {
                int p4 = t + (i << 8);
                *(float4*)&KVs[(p4 >> 6) * TK + ((p4 & 63) << 2)] = pf[i];
            }
            if (c < NCH - 1) {
#pragma unroll
                for (int i = 0; i < 16; i++) {
                    int p4 = t + (i << 8);
                    pf[i] = *(const float4*)&Ktg[(size_t)(p4 >> 6) * S + kc + TK + ((p4 & 63) << 2)];
                }
            } else {
#pragma unroll
                for (int i = 0; i < 16; i++) {
                    int p4 = t + (i << 8);
                    pf[i] = *(const float4*)&Vg[(size_t)(p4 >> 4) * DK + ((p4 & 15) << 2)];
                }
            }
            __syncthreads();

            float acc[4][4];
#pragma unroll
            for (int i = 0; i < 4; i++)
#pragma unroll
                for (int j = 0; j < 4; j++) acc[i][j] = 0.f;

#pragma unroll
            for (int d = 0; d < DK; d++) {
                const float4 kv = *(const float4*)&KVs[d * TK + (ki << 2)];
                const float4 qv = *(const float4*)&Qs[d * 20 + (qi << 2)];
                acc[0][0] = fmaf(qv.x, kv.x, acc[0][0]);
                acc[0][1] = fmaf(qv.x, kv.y, acc[0][1]);
                acc[0][2] = fmaf(qv.x, kv.z, acc[0][2]);
                acc[0][3] = fmaf(qv.x, kv.w, acc[0][3]);
                acc[1][0] = fmaf(qv.y, kv.x, acc[1][0]);
                acc[1][1] = fmaf(qv.y, kv.y, acc[1][1]);
                acc[1][2] = fmaf(qv.y, kv.z, acc[1][2]);
                acc[1][3] = fmaf(qv.y, kv.w, acc[1][3]);
                acc[2][0] = fmaf(qv.z, kv.x, acc[2][0]);
                acc[2][1] = fmaf(qv.z, kv.y, acc[2][1]);
                acc[2][2] = fmaf(qv.z, kv.z, acc[2][2]);
                acc[2][3] = fmaf(qv.z, kv.w, acc[2][3]);
                acc[3][0] = fmaf(qv.w, kv.x, acc[3][0]);
                acc[3][1] = fmaf(qv.w, kv.y, acc[3][1]);
                acc[3][2] = fmaf(qv.w, kv.z, acc[3][2]);
                acc[3][3] = fmaf(qv.w, kv.w, acc[3][3]);
            }

#pragma unroll
            for (int i = 0; i < 4; i++) {
                const int q = (qi << 2) + i;
                const float4 mk = *(const float4*)&mask[(size_t)(q0 + q) * S + kc + (ki << 2)];
                float4 o;
                o.x = fmaf(acc[i][0], SCALE, mk.x);
                o.y = fmaf(acc[i][1], SCALE, mk.y);
                o.z = fmaf(acc[i][2], SCALE, mk.z);
                o.w = fmaf(acc[i][3], SCALE, mk.w);
                *(float4*)&Ss[q * SROW + kc + (ki << 2)] = o;
            }
        }
        __syncthreads();

#pragma unroll
        for (int i = 0; i < 16; i++) {
            int p4 = t + (i << 8);
            *(float4*)&KVs[(p4 >> 4) * DK + ((p4 & 15) << 2)] = pf[i];
        }
#pragma unroll
        for (int i = 0; i < 16; i++) {
            int p4 = t + (i << 8);
            pf[i] = *(const float4*)&Vg[(size_t)(TK + (p4 >> 4)) * DK + ((p4 & 15) << 2)];
        }

#pragma unroll
        for (int rr = 0; rr < 2; rr++) {
            const int q = w * 2 + rr;
            float* row = Ss + q * SROW;
            float m = -1e30f;
            for (int i = lane; i < S; i += 32) m = fmaxf(m, row[i]);
#pragma unroll
            for (int o = 16; o; o >>= 1) m = fmaxf(m, __shfl_xor_sync(0xFFFFFFFFu, m, o));
            float l = 0.f;
            for (int i = lane; i < S; i += 32) {
                float e = __expf(row[i] - m);
                row[i] = e;
                l += e;
            }
#pragma unroll
            for (int o = 16; o; o >>= 1) l += __shfl_xor_sync(0xFFFFFFFFu, l, o);
            const float inv = 1.f / l;

            float* __restrict__ arow = attn_dst + ((size_t)b * S + q0 + q) * S;
            for (int i = lane * 4; i < S; i += 128) {
                float4 e = *(float4*)&row[i];
                e.x *= inv; e.y *= inv; e.z *= inv; e.w *= inv;
                *(float4*)&row[i] = e;
                float4 a;
                a.x = e.x * 0.125f; a.y = e.y * 0.125f;
                a.z = e.z * 0.125f; a.w = e.w * 0.125f;
                if (hh > 0) {
                    float4 prev = *(float4*)&arow[i];
                    a.x += prev.x; a.y += prev.y; a.z += prev.z; a.w += prev.w;
                }
                *(float4*)&arow[i] = a;
            }
        }
        __syncthreads();

        float4 cacc[4];
#pragma unroll
        for (int i = 0; i < 4; i++) cacc[i] = make_float4(0.f, 0.f, 0.f, 0.f);

        for (int c = 0; c < NCH; c++) {
            const int vc = c * TK;
            const int kb = vc + (kq << 6);
#pragma unroll
            for (int kk = 0; kk < 64; kk += 4) {
                const float4 v0 = *(const float4*)&KVs[((kq << 6) + kk + 0) * DK + cg4];
                const float4 v1 = *(const float4*)&KVs[((kq << 6) + kk + 1) * DK + cg4];
                const float4 v2 = *(const float4*)&KVs[((kq << 6) + kk + 2) * DK + cg4];
                const float4 v3 = *(const float4*)&KVs[((kq << 6) + kk + 3) * DK + cg4];
#pragma unroll
                for (int i = 0; i < 4; i++) {
                    const float4 p = *(const float4*)&Ss[(qg4 + i) * SROW + kb + kk];
                    cacc[i].x = fmaf(p.x, v0.x, cacc[i].x);
                    cacc[i].y = fmaf(p.x, v0.y, cacc[i].y);
                    cacc[i].z = fmaf(p.x, v0.z, cacc[i].z);
                    cacc[i].w = fmaf(p.x, v0.w, cacc[i].w);
                    cacc[i].x = fmaf(p.y, v1.x, cacc[i].x);
                    cacc[i].y = fmaf(p.y, v1.y, cacc[i].y);
                    cacc[i].z = fmaf(p.y, v1.z, cacc[i].z);
                    cacc[i].w = fmaf(p.y, v1.w, cacc[i].w);
                    cacc[i].x = fmaf(p.z, v2.x, cacc[i].x);
                    cacc[i].y = fmaf(p.z, v2.y, cacc[i].y);
                    cacc[i].z = fmaf(p.z, v2.z, cacc[i].z);
                    cacc[i].w = fmaf(p.z, v2.w, cacc[i].w);
                    cacc[i].x = fmaf(p.w, v3.x, cacc[i].x);
                    cacc[i].y = fmaf(p.w, v3.y, cacc[i].y);
                    cacc[i].z = fmaf(p.w, v3.z, cacc[i].z);
                    cacc[i].w = fmaf(p.w, v3.w, cacc[i].w);
                }
            }
            if (c < NCH - 1) {
                __syncthreads();
#pragma unroll
                for (int i = 0; i < 16; i++) {
                    int p4 = t + (i << 8);
                    *(float4*)&KVs[(p4 >> 4) * DK + ((p4 & 15) << 2)] = pf[i];
                }
                if (c < NCH - 2) {
#pragma unroll
                    for (int i = 0; i < 16; i++) {
                        int p4 = t + (i << 8);
                        pf[i] = *(const float4*)&Vg[(size_t)((vc + 2 * TK) + (p4 >> 4)) * DK + ((p4 & 15) << 2)];
                    }
                }
                __syncthreads();
            }
        }

        __syncthreads();
#pragma unroll
        for (int i = 0; i < 4; i++)
            *(float4*)&KVs[(kq << 10) + (qg4 + i) * DK + cg4] = cacc[i];
        __syncthreads();
        {
            const int q  = t >> 4;
            const int c4 = (t & 15) << 2;
            float4 s0 = *(const float4*)&KVs[0 * 1024 + q * DK + c4];
            float4 s1 = *(const float4*)&KVs[1 * 1024 + q * DK + c4];
            float4 s2 = *(const float4*)&KVs[2 * 1024 + q * DK + c4];
            float4 s3 = *(const float4*)&KVs[3 * 1024 + q * DK + c4];
            float4 o;
            o.x = (s0.x + s1.x) + (s2.x + s3.x);
            o.y = (s0.y + s1.y) + (s2.y + s3.y);
            o.z = (s0.z + s1.z) + (s2.z + s3.z);
            o.w = (s0.w + s1.w) + (s2.w + s3.w);
            *(float4*)&g_ctx[((size_t)b * S + q0 + q) * D + h * DK + c4] = o;
        }
    }
}

// ---------------------------------------------------------------------------
// K3: attn_out += g_attn2
// ---------------------------------------------------------------------------
__global__ __launch_bounds__(256) void k3_merge(float* __restrict__ attn_out)
{
    using namespace cfg;
    const size_t i4 = (size_t)blockIdx.x * 256 + threadIdx.x;
    float4 a = ((const float4*)g_attn2)[i4];
    float4 o = ((float4*)attn_out)[i4];
    o.x += a.x; o.y += a.y; o.z += a.z; o.w += a.w;
    ((float4*)attn_out)[i4] = o;
}

// ---------------------------------------------------------------------------
// K5: out[8192,512] = ctx @ Wout, FFMA2 inner loop.
// ---------------------------------------------------------------------------
__global__ __launch_bounds__(256) void k5_out(
    const float* __restrict__ Wout, float* __restrict__ out)
{
    using namespace cfg;
    constexpr int BM = 128, BN = 128, BK = 16;
    __shared__ float As[BK][BM + 4];
    __shared__ float Bs[BK][BN];

    const int row0 = blockIdx.x * BM;
    const int col0 = blockIdx.y * BN;
    const int t  = threadIdx.x;
    const int tm = (t >> 4) << 3;
    const int tn = (t & 15) << 3;

    unsigned long long acc2[8][4];
#pragma unroll
    for (int i = 0; i < 8; i++)
#pragma unroll
        for (int j = 0; j < 4; j++) acc2[i][j] = 0ULL;

    for (int k0 = 0; k0 < D; k0 += BK) {
#pragma unroll
        for (int i = 0; i < 8; i++) {
            int p = t + i * 256;
            int m = p >> 4, k = p & 15;
            As[k][m] = g_ctx[(size_t)(row0 + m) * D + k0 + k];
        }
#pragma unroll
        for (int i = 0; i < 8; i++) {
            int p = t + i * 256;
            int k = p >> 7, n = p & 127;
            Bs[k][n] = Wout[(size_t)(k0 + k) * D + col0 + n];
        }
        __syncthreads();
#pragma unroll
        for (int k = 0; k < BK; k++) {
            const ulonglong2 bl = *(const ulonglong2*)&Bs[k][tn];
            const ulonglong2 bh = *(const ulonglong2*)&Bs[k][tn + 4];
            const unsigned long long bb0 = bl.x, bb1 = bl.y;
            const unsigned long long bb2 = bh.x, bb3 = bh.y;
            float a[8];
#pragma unroll
            for (int i = 0; i < 8; i++) a[i] = As[k][tm + i];
#pragma unroll
            for (int i = 0; i < 8; i++) {
                const unsigned long long aa = pack2(a[i]);
                ffma2(acc2[i][0], aa, bb0);
                ffma2(acc2[i][1], aa, bb1);
                ffma2(acc2[i][2], aa, bb2);
                ffma2(acc2[i][3], aa, bb3);
            }
        }
        __syncthreads();
    }
#pragma unroll
    for (int i = 0; i < 8; i++) {
        const int r = row0 + tm + i;
#pragma unroll
        for (int jp = 0; jp < 4; jp++) {
            const float2 v2 = unpack2(acc2[i][jp]);
            *(float2*)&out[(size_t)r * D + col0 + tn + 2 * jp] = v2;
        }
    }
}

// ---------------------------------------------------------------------------
namespace {
struct CudaWarm {
    CudaWarm() {
        cudaFuncSetAttribute(k2_attn,
            cudaFuncAttributeMaxDynamicSharedMemorySize, cfg::SMEM2);
        cudaFuncAttributes a;
        cudaFuncGetAttributes(&a, (const void*)k1_qkv);
        cudaFuncGetAttributes(&a, (const void*)k2_attn);
        cudaFuncGetAttributes(&a, (const void*)k3_merge);
        cudaFuncGetAttributes(&a, (const void*)k5_out);
    }
};
CudaWarm g_warm;
}

// ---------------------------------------------------------------------------
extern "C" void kernel_launch(void* const* d_in, const int* in_sizes, int n_in,
                              void* d_out, int out_size)
{
    using namespace cfg;
    const float* Zq   = (const float*)d_in[0];
    const float* Zkv  = (const float*)d_in[1];
    const float* mask = (const float*)d_in[2];
    const float* Wqkv = (const float*)d_in[3];
    const float* Wout = (const float*)d_in[4];

    float* out       = (float*)d_out;
    float* attn_mean = out + (size_t)B * S * D;

    cudaFuncSetAttribute(k2_attn,
        cudaFuncAttributeMaxDynamicSharedMemorySize, SMEM2);

    k1_qkv<<<dim3(MROWS / 128, N3 / 128), 256>>>(Zq, Zkv, Wqkv);
    k2_attn<<<dim3(S / TQ, B, 2), 256, SMEM2>>>(mask, attn_mean);
    k3_merge<<<(int)((size_t)B * S * S / 4 / 256), 256>>>(attn_mean);
    k5_out<<<dim3(MROWS / 128, D / 128), 256>>>(Wout, out);
}

// round 9
// speedup vs baseline: 1.0418x; 1.0418x over previous
#include <cuda_runtime.h>
#include <math.h>
#include <stdint.h>

// ---------------------------------------------------------------------------
// MultiHeadCrossAttentionBlock: B=4, S=2048, D=512, H=8, DK=64
// d_out = out [B,S,D] ++ attn.mean(axis=1) [B,S,S]
//
// Round 8:
//  * k1 reverted to plain FFMA (FFMA2 measured as NO FLOP gain on sm_103a:
//    2 MACs/instr at ~half issue rate; k5 keeps it only because measured
//    114us < 126us via fewer instrs, k1's scatter epilogue made it a loss).
//  * k2: pipelined staging (QK d-half split, PV 128-row double-buffered
//    chunks), register-tracked row max (softmax max pass deleted),
//    deferred 1/l normalization (PV uses raw exp, ctx scaled at end).
// ---------------------------------------------------------------------------

namespace cfg {
constexpr int B  = 4;
constexpr int S  = 2048;
constexpr int D  = 512;
constexpr int H  = 8;
constexpr int DK = 64;
constexpr int N3 = 3 * D;          // 1536
constexpr int MROWS = B * S;       // 8192
constexpr float SCALE = 0.125f;
constexpr int TQ = 16;
constexpr int TK = 256;            // QK k-chunk
constexpr int NCH = S / TK;        // 8
constexpr int VCH = 128;           // PV k-chunk (double-buffered)
constexpr int NVC = S / VCH;       // 16
constexpr int SROW = S + 4;
constexpr int SMEM2_FLOATS = TQ * SROW + DK * TK + DK * 20 + 64;
constexpr int SMEM2 = SMEM2_FLOATS * 4;
constexpr int HGRP = H / 2;
}

// ------------------------------ scratch ------------------------------------
__device__ float g_Q [cfg::B * cfg::H * cfg::S * cfg::DK];
__device__ float g_Kt[cfg::B * cfg::H * cfg::DK * cfg::S];
__device__ float g_V [cfg::B * cfg::H * cfg::S * cfg::DK];
__device__ float g_ctx[cfg::B * cfg::S * cfg::D];
__device__ float g_attn2[(size_t)cfg::B * cfg::S * cfg::S];

// ---------------------------------------------------------------------------
// packed f32x2 helpers (kept for k5 only)
// ---------------------------------------------------------------------------
__device__ __forceinline__ void ffma2(unsigned long long& d,
                                      unsigned long long a,
                                      unsigned long long b) {
    asm("fma.rn.f32x2 %0, %1, %2, %0;" : "+l"(d) : "l"(a), "l"(b));
}
__device__ __forceinline__ unsigned long long pack2(float x) {
    unsigned long long r;
    asm("mov.b64 %0, {%1, %1};" : "=l"(r) : "f"(x));
    return r;
}
__device__ __forceinline__ float2 unpack2(unsigned long long v) {
    float lo, hi;
    asm("mov.b64 {%0, %1}, %2;" : "=f"(lo), "=f"(hi) : "l"(v));
    return make_float2(lo, hi);
}

// ---------------------------------------------------------------------------
// K1: QKV projection (plain FFMA, round-5 version — measured at the roof)
// ---------------------------------------------------------------------------
__global__ __launch_bounds__(256) void k1_qkv(
    const float* __restrict__ Zq, const float* __restrict__ Zkv,
    const float* __restrict__ W)
{
    using namespace cfg;
    constexpr int BM = 128, BN = 128, BK = 16;
    __shared__ float As[BK][BM + 4];
    __shared__ float Bs[BK][BN];

    const int row0 = blockIdx.x * BM;
    const int col0 = blockIdx.y * BN;
    const float* __restrict__ Z = (col0 < D) ? Zq : Zkv;

    const int t  = threadIdx.x;
    const int tm = (t >> 4) << 3;
    const int tn = (t & 15) << 3;

    float acc[8][8];
#pragma unroll
    for (int i = 0; i < 8; i++)
#pragma unroll
        for (int j = 0; j < 8; j++) acc[i][j] = 0.f;

    for (int k0 = 0; k0 < D; k0 += BK) {
#pragma unroll
        for (int i = 0; i < 8; i++) {
            int p = t + i * 256;
            int m = p >> 4, k = p & 15;
            As[k][m] = Z[(size_t)(row0 + m) * D + k0 + k];
        }
#pragma unroll
        for (int i = 0; i < 8; i++) {
            int p = t + i * 256;
            int k = p >> 7, n = p & 127;
            Bs[k][n] = W[(size_t)(k0 + k) * N3 + col0 + n];
        }
        __syncthreads();
#pragma unroll
        for (int k = 0; k < BK; k++) {
            float a[8], b[8];
#pragma unroll
            for (int i = 0; i < 8; i++) a[i] = As[k][tm + i];
#pragma unroll
            for (int j = 0; j < 8; j++) b[j] = Bs[k][tn + j];
#pragma unroll
            for (int i = 0; i < 8; i++)
#pragma unroll
                for (int j = 0; j < 8; j++)
                    acc[i][j] = fmaf(a[i], b[j], acc[i][j]);
        }
        __syncthreads();
    }

    const int part = col0 / D;
#pragma unroll
    for (int i = 0; i < 8; i++) {
        const int r = row0 + tm + i;
        const int b = r >> 11, s = r & (S - 1);
#pragma unroll
        for (int j = 0; j < 8; j++) {
            const int c  = col0 + tn + j - part * D;
            const int h  = c >> 6, dk = c & 63;
            const float v = acc[i][j];
            if (part == 0)      g_Q [((size_t)(b * H + h) * S  + s)  * DK + dk] = v;
            else if (part == 1) g_Kt[((size_t)(b * H + h) * DK + dk) * S  + s ] = v;
            else                g_V [((size_t)(b * H + h) * S  + s)  * DK + dk] = v;
        }
    }
}

// ---------------------------------------------------------------------------
// K2: fused attention, pipelined staging + fused max + deferred normalize.
// Grid (128, 4, 2), 256 threads.
// smem: Ss[16][SROW] | KVs[16384] | Qs[64*20] | Rb[32] | Lb[16]
// ---------------------------------------------------------------------------
__global__ __launch_bounds__(256, 1) void k2_attn(
    const float* __restrict__ mask, float* __restrict__ attn_out)
{
    using namespace cfg;
    extern __shared__ float sm[];
    float* Ss  = sm;                       // scores / exp values
    float* KVs = Ss + TQ * SROW;           // QK: [64][256]; PV: 2 x [128][64]; partials
    float* Qs  = KVs + DK * TK;            // [64][20] d-major Q tile
    float* Rb  = Qs + DK * 20;             // 32 floats: per-(qi,warp-half) row maxes
    float* Lb  = Rb + 32;                  // 16 floats: 1/l per q row

    const int qt = blockIdx.x;
    const int b  = blockIdx.y;
    const int hz = blockIdx.z;
    const int h0 = hz * HGRP;
    const int q0 = qt * TQ;
    const int t  = threadIdx.x;

    float* __restrict__ attn_dst = (hz == 0) ? attn_out : g_attn2;

    const int qi = t >> 6;                 // 0..3 (QK q-group; also PV k-quarter)
    const int ki = t & 63;
    const int qg4 = ((t >> 4) & 3) << 2;   // PV q row base
    const int cg4 = (t & 15) << 2;         // PV col base
    const int w = t >> 5, lane = t & 31;

    float4 pf[16];

    for (int hh = 0; hh < HGRP; hh++) {
        const int h  = h0 + hh;
        const int bh = b * H + h;
        const float* __restrict__ Qg  = g_Q  + ((size_t)bh * S + q0) * DK;
        const float* __restrict__ Ktg = g_Kt + (size_t)bh * DK * S;
        const float* __restrict__ Vg  = g_V  + (size_t)bh * S * DK;

        // ---- Q tile transposed into smem ----
#pragma unroll
        for (int i = 0; i < 4; i++) {
            int p = t + i * 256;
            Qs[(p & 63) * 20 + (p >> 6)] = Qg[(p >> 6) * DK + (p & 63)];
        }
        // prefetch K chunk 0
#pragma unroll
        for (int i = 0; i < 16; i++) {
            int p4 = t + (i << 8);
            pf[i] = *(const float4*)&Ktg[(size_t)(p4 >> 6) * S + ((p4 & 63) << 2)];
        }
        __syncthreads();                   // (prev head's KVs readers done; Qs pending)
        // pre-stage half0 (d 0..31) of chunk 0
#pragma unroll
        for (int i = 0; i < 8; i++) {
            int p4 = t + (i << 8);
            *(float4*)&KVs[(p4 >> 6) * TK + ((p4 & 63) << 2)] = pf[i];
        }

        float rmax[4] = {-1e30f, -1e30f, -1e30f, -1e30f};

        // ================= QK^T: 8 chunks, d-half pipelined =================
        for (int c = 0; c < NCH; c++) {
            __syncthreads();               // S1: half0(c) visible; d32..63 free
#pragma unroll
            for (int i = 8; i < 16; i++) { // stage half1 (d 32..63)
                int p4 = t + (i << 8);
                *(float4*)&KVs[(p4 >> 6) * TK + ((p4 & 63) << 2)] = pf[i];
            }

            float acc[4][4];
#pragma unroll
            for (int i = 0; i < 4; i++)
#pragma unroll
                for (int j = 0; j < 4; j++) acc[i][j] = 0.f;

#pragma unroll
            for (int d = 0; d < 32; d++) { // compute half0
                const float4 kv = *(const float4*)&KVs[d * TK + (ki << 2)];
                const float4 qv = *(const float4*)&Qs[d * 20 + (qi << 2)];
                acc[0][0] = fmaf(qv.x, kv.x, acc[0][0]);
                acc[0][1] = fmaf(qv.x, kv.y, acc[0][1]);
                acc[0][2] = fmaf(qv.x, kv.z, acc[0][2]);
                acc[0][3] = fmaf(qv.x, kv.w, acc[0][3]);
                acc[1][0] = fmaf(qv.y, kv.x, acc[1][0]);
                acc[1][1] = fmaf(qv.y, kv.y, acc[1][1]);
                acc[1][2] = fmaf(qv.y, kv.z, acc[1][2]);
                acc[1][3] = fmaf(qv.y, kv.w, acc[1][3]);
                acc[2][0] = fmaf(qv.z, kv.x, acc[2][0]);
                acc[2][1] = fmaf(qv.z, kv.y, acc[2][1]);
                acc[2][2] = fmaf(qv.z, kv.z, acc[2][2]);
                acc[2][3] = fmaf(qv.z, kv.w, acc[2][3]);
                acc[3][0] = fmaf(qv.w, kv.x, acc[3][0]);
                acc[3][1] = fmaf(qv.w, kv.y, acc[3][1]);
                acc[3][2] = fmaf(qv.w, kv.z, acc[3][2]);
                acc[3][3] = fmaf(qv.w, kv.w, acc[3][3]);
            }

            // prefetch next K chunk, or first V chunk (128 rows, 8 float4)
            if (c < NCH - 1) {
#pragma unroll
                for (int i = 0; i < 16; i++) {
                    int p4 = t + (i << 8);
                    pf[i] = *(const float4*)&Ktg[(size_t)(p4 >> 6) * S + (c + 1) * TK + ((p4 & 63) << 2)];
                }
            } else {
#pragma unroll
                for (int i = 0; i < 8; i++) {
                    int p4 = t + (i << 8);
                    pf[i] = *(const float4*)&Vg[(size_t)(p4 >> 4) * DK + ((p4 & 15) << 2)];
                }
            }

            __syncthreads();               // S2: half1 visible; d0..31 free
            if (c < NCH - 1) {
#pragma unroll
                for (int i = 0; i < 8; i++) {  // stage half0 of chunk c+1
                    int p4 = t + (i << 8);
                    *(float4*)&KVs[(p4 >> 6) * TK + ((p4 & 63) << 2)] = pf[i];
                }
            }

#pragma unroll
            for (int d = 32; d < 64; d++) { // compute half1
                const float4 kv = *(const float4*)&KVs[d * TK + (ki << 2)];
                const float4 qv = *(const float4*)&Qs[d * 20 + (qi << 2)];
                acc[0][0] = fmaf(qv.x, kv.x, acc[0][0]);
                acc[0][1] = fmaf(qv.x, kv.y, acc[0][1]);
                acc[0][2] = fmaf(qv.x, kv.z, acc[0][2]);
                acc[0][3] = fmaf(qv.x, kv.w, acc[0][3]);
                acc[1][0] = fmaf(qv.y, kv.x, acc[1][0]);
                acc[1][1] = fmaf(qv.y, kv.y, acc[1][1]);
                acc[1][2] = fmaf(qv.y, kv.z, acc[1][2]);
                acc[1][3] = fmaf(qv.y, kv.w, acc[1][3]);
                acc[2][0] = fmaf(qv.z, kv.x, acc[2][0]);
                acc[2][1] = fmaf(qv.z, kv.y, acc[2][1]);
                acc[2][2] = fmaf(qv.z, kv.z, acc[2][2]);
                acc[2][3] = fmaf(qv.z, kv.w, acc[2][3]);
                acc[3][0] = fmaf(qv.w, kv.x, acc[3][0]);
                acc[3][1] = fmaf(qv.w, kv.y, acc[3][1]);
                acc[3][2] = fmaf(qv.w, kv.z, acc[3][2]);
                acc[3][3] = fmaf(qv.w, kv.w, acc[3][3]);
            }

            // epilogue: scores + mask -> Ss, track row max in registers
#pragma unroll
            for (int i = 0; i < 4; i++) {
                const int q = (qi << 2) + i;
                const float4 mk = *(const float4*)&mask[(size_t)(q0 + q) * S + c * TK + (ki << 2)];
                float4 o;
                o.x = fmaf(acc[i][0], SCALE, mk.x);
                o.y = fmaf(acc[i][1], SCALE, mk.y);
                o.z = fmaf(acc[i][2], SCALE, mk.z);
                o.w = fmaf(acc[i][3], SCALE, mk.w);
                *(float4*)&Ss[q * SROW + c * TK + (ki << 2)] = o;
                rmax[i] = fmaxf(rmax[i], fmaxf(fmaxf(o.x, o.y), fmaxf(o.z, o.w)));
            }
        }

        // ---- row-max reduce: warp shuffle, then 2-warp combine via Rb ----
#pragma unroll
        for (int j = 0; j < 4; j++) {
            float m = rmax[j];
#pragma unroll
            for (int o = 16; o; o >>= 1) m = fmaxf(m, __shfl_xor_sync(0xFFFFFFFFu, m, o));
            rmax[j] = m;
        }
        if (lane == 0) {
#pragma unroll
            for (int j = 0; j < 4; j++) Rb[qi * 8 + (w & 1) * 4 + j] = rmax[j];
        }
        __syncthreads();                   // S3: Ss + Rb complete; KVs free

        // stage V chunk 0 into buf0; prefetch V chunk 1
#pragma unroll
        for (int i = 0; i < 8; i++) {
            int p4 = t + (i << 8);
            *(float4*)&KVs[(p4 >> 4) * DK + ((p4 & 15) << 2)] = pf[i];
        }
#pragma unroll
        for (int i = 0; i < 8; i++) {
            int p4 = t + (i << 8);
            pf[i] = *(const float4*)&Vg[(size_t)(VCH + (p4 >> 4)) * DK + ((p4 & 15) << 2)];
        }

        // ---- softmax (no max pass, no normalized write-back) ----
#pragma unroll
        for (int rr = 0; rr < 2; rr++) {
            const int q = w * 2 + rr;
            float* row = Ss + q * SROW;
            const float m = fmaxf(Rb[(q >> 2) * 8 + (q & 3)],
                                  Rb[(q >> 2) * 8 + 4 + (q & 3)]);
            float l = 0.f;
            for (int i = lane; i < S; i += 32) {
                float e = __expf(row[i] - m);
                row[i] = e;                        // raw exp stays in smem
                l += e;
            }
#pragma unroll
            for (int o = 16; o; o >>= 1) l += __shfl_xor_sync(0xFFFFFFFFu, l, o);
            const float inv = 1.f / l;
            if (lane == 0) Lb[q] = inv;
            const float invk = inv * 0.125f;

            float* __restrict__ arow = attn_dst + ((size_t)b * S + q0 + q) * S;
            for (int i = lane * 4; i < S; i += 128) {
                float4 e = *(float4*)&row[i];
                float4 a;
                a.x = e.x * invk; a.y = e.y * invk;
                a.z = e.z * invk; a.w = e.w * invk;
                if (hh > 0) {
                    float4 prev = *(float4*)&arow[i];
                    a.x += prev.x; a.y += prev.y; a.z += prev.z; a.w += prev.w;
                }
                *(float4*)&arow[i] = a;
            }
        }
        __syncthreads();                   // S4: V buf0 + Lb visible

        // ================= PV: 16 chunks of 128 rows, double-buffered =======
        float4 cacc[4];
#pragma unroll
        for (int i = 0; i < 4; i++) cacc[i] = make_float4(0.f, 0.f, 0.f, 0.f);

        const int rb = qi << 5;            // this thread's 32-row window in chunk
        for (int c = 0; c < NVC; c++) {
            const float* buf = KVs + (c & 1) * 8192;
            if (c < NVC - 1) {
                float* nbuf = KVs + ((c + 1) & 1) * 8192;
#pragma unroll
                for (int i = 0; i < 8; i++) {
                    int p4 = t + (i << 8);
                    *(float4*)&nbuf[(p4 >> 4) * DK + ((p4 & 15) << 2)] = pf[i];
                }
            }
            if (c < NVC - 2) {
#pragma unroll
                for (int i = 0; i < 8; i++) {
                    int p4 = t + (i << 8);
                    pf[i] = *(const float4*)&Vg[(size_t)((c + 2) * VCH + (p4 >> 4)) * DK + ((p4 & 15) << 2)];
                }
            }
#pragma unroll
            for (int kk = 0; kk < 32; kk += 4) {
                const float4 v0 = *(const float4*)&buf[(rb + kk + 0) * DK + cg4];
                const float4 v1 = *(const float4*)&buf[(rb + kk + 1) * DK + cg4];
                const float4 v2 = *(const float4*)&buf[(rb + kk + 2) * DK + cg4];
                const float4 v3 = *(const float4*)&buf[(rb + kk + 3) * DK + cg4];
#pragma unroll
                for (int i = 0; i < 4; i++) {
                    const float4 p = *(const float4*)&Ss[(qg4 + i) * SROW + c * VCH + rb + kk];
                    cacc[i].x = fmaf(p.x, v0.x, cacc[i].x);
                    cacc[i].y = fmaf(p.x, v0.y, cacc[i].y);
                    cacc[i].z = fmaf(p.x, v0.z, cacc[i].z);
                    cacc[i].w = fmaf(p.x, v0.w, cacc[i].w);
                    cacc[i].x = fmaf(p.y, v1.x, cacc[i].x);
                    cacc[i].y = fmaf(p.y, v1.y, cacc[i].y);
                    cacc[i].z = fmaf(p.y, v1.z, cacc[i].z);
                    cacc[i].w = fmaf(p.y, v1.w, cacc[i].w);
                    cacc[i].x = fmaf(p.z, v2.x, cacc[i].x);
                    cacc[i].y = fmaf(p.z, v2.y, cacc[i].y);
                    cacc[i].z = fmaf(p.z, v2.z, cacc[i].z);
                    cacc[i].w = fmaf(p.z, v2.w, cacc[i].w);
                    cacc[i].x = fmaf(p.w, v3.x, cacc[i].x);
                    cacc[i].y = fmaf(p.w, v3.y, cacc[i].y);
                    cacc[i].z = fmaf(p.w, v3.z, cacc[i].z);
                    cacc[i].w = fmaf(p.w, v3.w, cacc[i].w);
                }
            }
            __syncthreads();               // next chunk visible; buffers rotate
        }

        // ---- deferred normalization, then reduce 4 k-quarter partials ----
#pragma unroll
        for (int i = 0; i < 4; i++) {
            const float f = Lb[qg4 + i];
            cacc[i].x *= f; cacc[i].y *= f; cacc[i].z *= f; cacc[i].w *= f;
        }
#pragma unroll
        for (int i = 0; i < 4; i++)
            *(float4*)&KVs[(qi << 10) + (qg4 + i) * DK + cg4] = cacc[i];
        __syncthreads();
        {
            const int q  = t >> 4;
            const int c4 = (t & 15) << 2;
            float4 s0 = *(const float4*)&KVs[0 * 1024 + q * DK + c4];
            float4 s1 = *(const float4*)&KVs[1 * 1024 + q * DK + c4];
            float4 s2 = *(const float4*)&KVs[2 * 1024 + q * DK + c4];
            float4 s3 = *(const float4*)&KVs[3 * 1024 + q * DK + c4];
            float4 o;
            o.x = (s0.x + s1.x) + (s2.x + s3.x);
            o.y = (s0.y + s1.y) + (s2.y + s3.y);
            o.z = (s0.z + s1.z) + (s2.z + s3.z);
            o.w = (s0.w + s1.w) + (s2.w + s3.w);
            *(float4*)&g_ctx[((size_t)b * S + q0 + q) * D + h * DK + c4] = o;
        }
        // next head's first __syncthreads orders KVs reuse
    }
}

// ---------------------------------------------------------------------------
// K3: attn_out += g_attn2
// ---------------------------------------------------------------------------
__global__ __launch_bounds__(256) void k3_merge(float* __restrict__ attn_out)
{
    using namespace cfg;
    const size_t i4 = (size_t)blockIdx.x * 256 + threadIdx.x;
    float4 a = ((const float4*)g_attn2)[i4];
    float4 o = ((float4*)attn_out)[i4];
    o.x += a.x; o.y += a.y; o.z += a.z; o.w += a.w;
    ((float4*)attn_out)[i4] = o;
}

// ---------------------------------------------------------------------------
// K5: out = ctx @ Wout (FFMA2 version; measured 114us vs 126us FFMA)
// ---------------------------------------------------------------------------
__global__ __launch_bounds__(256) void k5_out(
    const float* __restrict__ Wout, float* __restrict__ out)
{
    using namespace cfg;
    constexpr int BM = 128, BN = 128, BK = 16;
    __shared__ float As[BK][BM + 4];
    __shared__ float Bs[BK][BN];

    const int row0 = blockIdx.x * BM;
    const int col0 = blockIdx.y * BN;
    const int t  = threadIdx.x;
    const int tm = (t >> 4) << 3;
    const int tn = (t & 15) << 3;

    unsigned long long acc2[8][4];
#pragma unroll
    for (int i = 0; i < 8; i++)
#pragma unroll
        for (int j = 0; j < 4; j++) acc2[i][j] = 0ULL;

    for (int k0 = 0; k0 < D; k0 += BK) {
#pragma unroll
        for (int i = 0; i < 8; i++) {
            int p = t + i * 256;
            int m = p >> 4, k = p & 15;
            As[k][m] = g_ctx[(size_t)(row0 + m) * D + k0 + k];
        }
#pragma unroll
        for (int i = 0; i < 8; i++) {
            int p = t + i * 256;
            int k = p >> 7, n = p & 127;
            Bs[k][n] = Wout[(size_t)(k0 + k) * D + col0 + n];
        }
        __syncthreads();
#pragma unroll
        for (int k = 0; k < BK; k++) {
            const ulonglong2 bl = *(const ulonglong2*)&Bs[k][tn];
            const ulonglong2 bh = *(const ulonglong2*)&Bs[k][tn + 4];
            float a[8];
#pragma unroll
            for (int i = 0; i < 8; i++) a[i] = As[k][tm + i];
#pragma unroll
            for (int i = 0; i < 8; i++) {
                const unsigned long long aa = pack2(a[i]);
                ffma2(acc2[i][0], aa, bl.x);
                ffma2(acc2[i][1], aa, bl.y);
                ffma2(acc2[i][2], aa, bh.x);
                ffma2(acc2[i][3], aa, bh.y);
            }
        }
        __syncthreads();
    }
#pragma unroll
    for (int i = 0; i < 8; i++) {
        const int r = row0 + tm + i;
#pragma unroll
        for (int jp = 0; jp < 4; jp++) {
            const float2 v2 = unpack2(acc2[i][jp]);
            *(float2*)&out[(size_t)r * D + col0 + tn + 2 * jp] = v2;
        }
    }
}

// ---------------------------------------------------------------------------
namespace {
struct CudaWarm {
    CudaWarm() {
        cudaFuncSetAttribute(k2_attn,
            cudaFuncAttributeMaxDynamicSharedMemorySize, cfg::SMEM2);
        cudaFuncAttributes a;
        cudaFuncGetAttributes(&a, (const void*)k1_qkv);
        cudaFuncGetAttributes(&a, (const void*)k2_attn);
        cudaFuncGetAttributes(&a, (const void*)k3_merge);
        cudaFuncGetAttributes(&a, (const void*)k5_out);
    }
};
CudaWarm g_warm;
}

// ---------------------------------------------------------------------------
extern "C" void kernel_launch(void* const* d_in, const int* in_sizes, int n_in,
                              void* d_out, int out_size)
{
    using namespace cfg;
    const float* Zq   = (const float*)d_in[0];
    const float* Zkv  = (const float*)d_in[1];
    const float* mask = (const float*)d_in[2];
    const float* Wqkv = (const float*)d_in[3];
    const float* Wout = (const float*)d_in[4];

    float* out       = (float*)d_out;
    float* attn_mean = out + (size_t)B * S * D;

    cudaFuncSetAttribute(k2_attn,
        cudaFuncAttributeMaxDynamicSharedMemorySize, SMEM2);

    k1_qkv<<<dim3(MROWS / 128, N3 / 128), 256>>>(Zq, Zkv, Wqkv);
    k2_attn<<<dim3(S / TQ, B, 2), 256, SMEM2>>>(mask, attn_mean);
    k3_merge<<<(int)((size_t)B * S * S / 4 / 256), 256>>>(attn_mean);
    k5_out<<<dim3(MROWS / 128, D / 128), 256>>>(Wout, out);
}